// round 4
// baseline (speedup 1.0000x reference)
#include <cuda_runtime.h>

typedef unsigned long long u64;

#define IN      6
#define H       64
#define BB      4096
#define TT      512
#define NOUT    3
#define BPT     7            // batches per thread
#define BTILE   28           // 4 batch-groups * 7
#define NTHREADS 256         // 64 units * 4 batch-groups
#define NGRID   147

// ---- shared memory layout (float units) ----
#define OFF_W1P   0                          // [k=128][j=64][g=4] floats (k<64: Wih1, k>=64: Whh1)
#define OFF_W0P   (OFF_W1P  + 128*64*4)      // [k=64][j=64][g=4]  Whh0
#define OFF_WX0P  (OFF_W0P  + 64*64*4)       // [k=6][j=64][g=4]   Wih0
#define OFF_HA    (OFF_WX0P + 6*64*4)        // [28][64] u64 duplicated pairs (2 floats each)
#define OFF_HB    (OFF_HA   + BTILE*H*2)
#define OFF_XS    (OFF_HB   + BTILE*H*2)     // [28][6] floats
#define SMEM_FLOATS (OFF_XS + BTILE*IN)      // 58024 floats = 232096 B

__device__ __forceinline__ float fexp2_(float x) {
    float y; asm("ex2.approx.f32 %0, %1;" : "=f"(y) : "f"(x)); return y;
}
__device__ __forceinline__ float frcp_(float x) {
    float y; asm("rcp.approx.f32 %0, %1;" : "=f"(y) : "f"(x)); return y;
}
__device__ __forceinline__ float sigm_(float x) {
    float e = fexp2_(-1.4426950408889634f * x);
    return frcp_(1.0f + e);
}
__device__ __forceinline__ float tanh_(float x) {
    float e = fexp2_(-2.8853900817779268f * x);
    return fmaf(2.0f, frcp_(1.0f + e), -1.0f);
}

// packed f32x2 fma: a += u * w (lane-wise)
__device__ __forceinline__ void ffma2(u64& a, u64 u, u64 w) {
    asm("fma.rn.f32x2 %0, %1, %2, %0;" : "+l"(a) : "l"(u), "l"(w));
}
__device__ __forceinline__ u64 packf2(float lo, float hi) {
    u64 r; asm("mov.b64 %0, {%1, %2};" : "=l"(r) : "f"(lo), "f"(hi)); return r;
}
__device__ __forceinline__ u64 dup2(float v) {
    u64 r; asm("mov.b64 %0, {%1, %1};" : "=l"(r) : "f"(v)); return r;
}
__device__ __forceinline__ void unpack2(u64 v, float& lo, float& hi) {
    asm("mov.b64 {%0, %1}, %2;" : "=f"(lo), "=f"(hi) : "l"(v));
}

// 64-deep K GEMM block, packed gates: aif[b] += h[k]*(Wi,Wf), ago[b] += h[k]*(Wg,Wo)
__device__ __forceinline__ void gemm2(
    u64 aif[BPT], u64 ago[BPT],
    const ulonglong2* __restrict__ Wq,   // [k][64] : (w_if, w_go) per (k,j)
    const ulonglong2* __restrict__ u2,   // [b][32] : ((h,h),(h,h)) pairs over k
    int j, int bl0)
{
#pragma unroll 2
    for (int k2 = 0; k2 < 32; ++k2) {
        ulonglong2 w0 = Wq[(2 * k2 + 0) * 64 + j];
        ulonglong2 w1 = Wq[(2 * k2 + 1) * 64 + j];
#pragma unroll
        for (int b = 0; b < BPT; ++b) {
            ulonglong2 u = u2[(bl0 + b) * 32 + k2];   // (dup h[2k2], dup h[2k2+1])
            ffma2(aif[b], u.x, w0.x);
            ffma2(ago[b], u.x, w0.y);
            ffma2(aif[b], u.y, w1.x);
            ffma2(ago[b], u.y, w1.y);
        }
    }
}

__device__ __forceinline__ float cellact2(u64 aif, u64 ago, float& c) {
    float ai, af, ag, ao;
    unpack2(aif, ai, af);
    unpack2(ago, ag, ao);
    float ig = sigm_(ai);
    float fg = sigm_(af);
    float gg = tanh_(ag);
    float og = sigm_(ao);
    c = fmaf(fg, c, ig * gg);
    return og * tanh_(c);
}

__global__ void __launch_bounds__(NTHREADS, 1)
lstm2_kernel(const float* __restrict__ x,
             const float* __restrict__ Wih0, const float* __restrict__ Whh0,
             const float* __restrict__ bih0, const float* __restrict__ bhh0,
             const float* __restrict__ Wih1, const float* __restrict__ Whh1,
             const float* __restrict__ bih1, const float* __restrict__ bhh1,
             const float* __restrict__ Wfc,  const float* __restrict__ bfc,
             float* __restrict__ out)
{
    extern __shared__ float sm[];
    const int tid = threadIdx.x;
    const int j   = tid & 63;        // hidden unit
    const int bg  = tid >> 6;        // batch group 0..3
    const int bl0 = bg * BPT;        // first local batch
    const int b0  = blockIdx.x * BTILE;

    // ---- pack weights into SMEM (gate-quad layout [k][j][g]) ----
    for (int idx = tid; idx < 128 * 64 * 4; idx += NTHREADS) {
        int g = idx & 3, jj = (idx >> 2) & 63, k = idx >> 8;
        sm[OFF_W1P + idx] = (k < 64) ? Wih1[(g * 64 + jj) * 64 + k]
                                     : Whh1[(g * 64 + jj) * 64 + (k - 64)];
    }
    for (int idx = tid; idx < 64 * 64 * 4; idx += NTHREADS) {
        int g = idx & 3, jj = (idx >> 2) & 63, k = idx >> 8;
        sm[OFF_W0P + idx] = Whh0[(g * 64 + jj) * 64 + k];
    }
    for (int idx = tid; idx < 6 * 64 * 4; idx += NTHREADS) {
        int g = idx & 3, jj = (idx >> 2) & 63, k = idx >> 8;
        sm[OFF_WX0P + idx] = Wih0[(g * 64 + jj) * 6 + k];
    }
    // zero both dup h arrays (contiguous: 4*BTILE*H floats)
    for (int idx = tid; idx < BTILE * H * 4; idx += NTHREADS)
        sm[OFF_HA + idx] = 0.0f;

    // per-thread biases from global (registers)
    const float bA0 = bih0[0 * 64 + j] + bhh0[0 * 64 + j];
    const float bA1 = bih0[1 * 64 + j] + bhh0[1 * 64 + j];
    const float bA2 = bih0[2 * 64 + j] + bhh0[2 * 64 + j];
    const float bA3 = bih0[3 * 64 + j] + bhh0[3 * 64 + j];
    const u64 bBif = packf2(bih1[0 * 64 + j] + bhh1[0 * 64 + j],
                            bih1[1 * 64 + j] + bhh1[1 * 64 + j]);
    const u64 bBgo = packf2(bih1[2 * 64 + j] + bhh1[2 * 64 + j],
                            bih1[3 * 64 + j] + bhh1[3 * 64 + j]);

    // x staging (threads 0..167 each own one (batch,feature) slot)
    const int xb = tid / IN;
    const int xf = tid - xb * IN;
    const bool xthr  = (tid < BTILE * IN);
    const bool xload = xthr && (b0 + xb < BB);
    float* XS = sm + OFF_XS;
    if (xthr) XS[tid] = xload ? x[((size_t)(b0 + xb) * TT + 0) * IN + xf] : 0.0f;

    __syncthreads();

    const ulonglong2* Wq1  = (const ulonglong2*)(sm + OFF_W1P);
    const ulonglong2* Wq0  = (const ulonglong2*)(sm + OFF_W0P);
    const float4*     Wx4  = (const float4*)(sm + OFF_WX0P);
    u64* hAu = (u64*)(sm + OFF_HA);
    u64* hBu = (u64*)(sm + OFF_HB);
    const ulonglong2* hA2 = (const ulonglong2*)(sm + OFF_HA);
    const ulonglong2* hB2 = (const ulonglong2*)(sm + OFF_HB);

    float cA[BPT], cB[BPT];
#pragma unroll
    for (int b = 0; b < BPT; ++b) { cA[b] = 0.f; cB[b] = 0.f; }

    for (int t = 0; t < TT; ++t) {
        // prefetch next x into register
        float xpre = 0.0f;
        if (t + 1 < TT && xload)
            xpre = x[((size_t)(b0 + xb) * TT + (t + 1)) * IN + xf];

        // ---------- layer 0: input part (scalar) + bias ----------
        float g0[BPT], g1[BPT], g2[BPT], g3[BPT];
#pragma unroll
        for (int b = 0; b < BPT; ++b) { g0[b] = bA0; g1[b] = bA1; g2[b] = bA2; g3[b] = bA3; }
#pragma unroll
        for (int k = 0; k < IN; ++k) {
            float4 w = Wx4[k * 64 + j];
#pragma unroll
            for (int b = 0; b < BPT; ++b) {
                float xv = XS[(bl0 + b) * IN + k];
                g0[b] = fmaf(xv, w.x, g0[b]);
                g1[b] = fmaf(xv, w.y, g1[b]);
                g2[b] = fmaf(xv, w.z, g2[b]);
                g3[b] = fmaf(xv, w.w, g3[b]);
            }
        }
        u64 aif[BPT], ago[BPT];
#pragma unroll
        for (int b = 0; b < BPT; ++b) {
            aif[b] = packf2(g0[b], g1[b]);
            ago[b] = packf2(g2[b], g3[b]);
        }
        // recurrent: Whh0 @ hA(t-1)
        gemm2(aif, ago, Wq0, hA2, j, bl0);

        float n[BPT];
#pragma unroll
        for (int b = 0; b < BPT; ++b) n[b] = cellact2(aif[b], ago[b], cA[b]);

        __syncthreads();                           // all reads of hA & XS done
#pragma unroll
        for (int b = 0; b < BPT; ++b) hAu[(bl0 + b) * H + j] = dup2(n[b]);
        if (xthr) XS[tid] = xpre;
        __syncthreads();                           // new hA / XS visible

        // ---------- layer 1 ----------
#pragma unroll
        for (int b = 0; b < BPT; ++b) { aif[b] = bBif; ago[b] = bBgo; }
        gemm2(aif, ago, Wq1,           hA2, j, bl0);   // Wih1 @ hA(t)
        gemm2(aif, ago, Wq1 + 64 * 64, hB2, j, bl0);   // Whh1 @ hB(t-1)

#pragma unroll
        for (int b = 0; b < BPT; ++b) n[b] = cellact2(aif[b], ago[b], cB[b]);

        __syncthreads();                           // all reads of hB done
#pragma unroll
        for (int b = 0; b < BPT; ++b) hBu[(bl0 + b) * H + j] = dup2(n[b]);
        // no sync here: next reads of hB happen after the 2 syncs above
    }

    // ---------- final FC: out = hB(T-1) @ Wfc^T + bfc ----------
    __syncthreads();                               // hB writes visible
    float* wfs = sm + OFF_HA;                      // reuse hA region
    if (tid < NOUT * H) wfs[tid] = Wfc[tid];
    if (tid < NOUT)     wfs[NOUT * H + tid] = bfc[tid];
    __syncthreads();

    if (j < NOUT) {
        const float* hBf = (const float*)hBu;      // dup pairs: stride 2 floats
#pragma unroll
        for (int b = 0; b < BPT; ++b) {
            int bglob = b0 + bl0 + b;
            if (bglob < BB) {
                float acc = wfs[NOUT * H + j];
                const float* wr = wfs + j * H;
                const float* hr = hBf + (bl0 + b) * H * 2;
#pragma unroll
                for (int k = 0; k < H; ++k) acc = fmaf(hr[2 * k], wr[k], acc);
                out[bglob * NOUT + j] = acc;
            }
        }
    }
}

extern "C" void kernel_launch(void* const* d_in, const int* in_sizes, int n_in,
                              void* d_out, int out_size)
{
    const float* x    = (const float*)d_in[0];
    const float* Wih0 = (const float*)d_in[1];
    const float* Whh0 = (const float*)d_in[2];
    const float* bih0 = (const float*)d_in[3];
    const float* bhh0 = (const float*)d_in[4];
    const float* Wih1 = (const float*)d_in[5];
    const float* Whh1 = (const float*)d_in[6];
    const float* bih1 = (const float*)d_in[7];
    const float* bhh1 = (const float*)d_in[8];
    const float* Wfc  = (const float*)d_in[9];
    const float* bfc  = (const float*)d_in[10];
    float* out = (float*)d_out;

    const size_t smem = (size_t)SMEM_FLOATS * sizeof(float);  // 232096 B
    cudaFuncSetAttribute(lstm2_kernel,
                         cudaFuncAttributeMaxDynamicSharedMemorySize, (int)smem);
    lstm2_kernel<<<NGRID, NTHREADS, smem>>>(x, Wih0, Whh0, bih0, bhh0,
                                            Wih1, Whh1, bih1, bhh1,
                                            Wfc, bfc, out);
}

// round 5
// speedup vs baseline: 1.0017x; 1.0017x over previous
#include <cuda_runtime.h>

typedef unsigned long long u64;

#define IN      6
#define H       64
#define BB      4096
#define TT      512
#define NOUT    3
#define BPT     7            // batches per thread
#define BTILE   28           // 4 batch-groups * 7
#define NTHREADS 256         // 64 units * 4 batch-groups
#define NGRID   147

// ---- shared memory layout (float units) ----
#define OFF_W1P   0                          // [k=128][j=64][g=4] floats (k<64: Wih1, k>=64: Whh1)
#define OFF_W0P   (OFF_W1P  + 128*64*4)      // [k=64][j=64][g=4]  Whh0
#define OFF_WX0P  (OFF_W0P  + 64*64*4)       // [k=6][j=64][g=4]   Wih0
#define OFF_HA    (OFF_WX0P + 6*64*4)        // [28][64] u64 duplicated pairs (2 floats each)
#define OFF_HB    (OFF_HA   + BTILE*H*2)
#define OFF_XS    (OFF_HB   + BTILE*H*2)     // [28][6] floats
#define SMEM_FLOATS (OFF_XS + BTILE*IN)      // 58024 floats = 232096 B

__device__ __forceinline__ float fexp2_(float x) {
    float y; asm("ex2.approx.f32 %0, %1;" : "=f"(y) : "f"(x)); return y;
}
__device__ __forceinline__ float frcp_(float x) {
    float y; asm("rcp.approx.f32 %0, %1;" : "=f"(y) : "f"(x)); return y;
}
__device__ __forceinline__ float sigm_(float x) {
    float e = fexp2_(-1.4426950408889634f * x);
    return frcp_(1.0f + e);
}
__device__ __forceinline__ float tanh_(float x) {
    float e = fexp2_(-2.8853900817779268f * x);
    return fmaf(2.0f, frcp_(1.0f + e), -1.0f);
}

// packed f32x2 fma: a += u * w (lane-wise)
__device__ __forceinline__ void ffma2(u64& a, u64 u, u64 w) {
    asm("fma.rn.f32x2 %0, %1, %2, %0;" : "+l"(a) : "l"(u), "l"(w));
}
__device__ __forceinline__ u64 packf2(float lo, float hi) {
    u64 r; asm("mov.b64 %0, {%1, %2};" : "=l"(r) : "f"(lo), "f"(hi)); return r;
}
__device__ __forceinline__ u64 dup2(float v) {
    u64 r; asm("mov.b64 %0, {%1, %1};" : "=l"(r) : "f"(v)); return r;
}
__device__ __forceinline__ void unpack2(u64 v, float& lo, float& hi) {
    asm("mov.b64 {%0, %1}, %2;" : "=f"(lo), "=f"(hi) : "l"(v));
}

// 64-deep K GEMM block, packed gates: aif[b] += h[k]*(Wi,Wf), ago[b] += h[k]*(Wg,Wo)
__device__ __forceinline__ void gemm2(
    u64 aif[BPT], u64 ago[BPT],
    const ulonglong2* __restrict__ Wq,   // [k][64] : (w_if, w_go) per (k,j)
    const ulonglong2* __restrict__ u2,   // [b][32] : ((h,h),(h,h)) pairs over k
    int j, int bl0)
{
#pragma unroll 2
    for (int k2 = 0; k2 < 32; ++k2) {
        ulonglong2 w0 = Wq[(2 * k2 + 0) * 64 + j];
        ulonglong2 w1 = Wq[(2 * k2 + 1) * 64 + j];
#pragma unroll
        for (int b = 0; b < BPT; ++b) {
            ulonglong2 u = u2[(bl0 + b) * 32 + k2];   // (dup h[2k2], dup h[2k2+1])
            ffma2(aif[b], u.x, w0.x);
            ffma2(ago[b], u.x, w0.y);
            ffma2(aif[b], u.y, w1.x);
            ffma2(ago[b], u.y, w1.y);
        }
    }
}

__device__ __forceinline__ float cellact2(u64 aif, u64 ago, float& c) {
    float ai, af, ag, ao;
    unpack2(aif, ai, af);
    unpack2(ago, ag, ao);
    float ig = sigm_(ai);
    float fg = sigm_(af);
    float gg = tanh_(ag);
    float og = sigm_(ao);
    c = fmaf(fg, c, ig * gg);
    return og * tanh_(c);
}

__global__ void __launch_bounds__(NTHREADS, 1)
lstm2_kernel(const float* __restrict__ x,
             const float* __restrict__ Wih0, const float* __restrict__ Whh0,
             const float* __restrict__ bih0, const float* __restrict__ bhh0,
             const float* __restrict__ Wih1, const float* __restrict__ Whh1,
             const float* __restrict__ bih1, const float* __restrict__ bhh1,
             const float* __restrict__ Wfc,  const float* __restrict__ bfc,
             float* __restrict__ out)
{
    extern __shared__ float sm[];
    const int tid = threadIdx.x;
    const int j   = tid & 63;        // hidden unit
    const int bg  = tid >> 6;        // batch group 0..3
    const int bl0 = bg * BPT;        // first local batch
    const int b0  = blockIdx.x * BTILE;

    // ---- pack weights into SMEM (gate-quad layout [k][j][g]) ----
    for (int idx = tid; idx < 128 * 64 * 4; idx += NTHREADS) {
        int g = idx & 3, jj = (idx >> 2) & 63, k = idx >> 8;
        sm[OFF_W1P + idx] = (k < 64) ? Wih1[(g * 64 + jj) * 64 + k]
                                     : Whh1[(g * 64 + jj) * 64 + (k - 64)];
    }
    for (int idx = tid; idx < 64 * 64 * 4; idx += NTHREADS) {
        int g = idx & 3, jj = (idx >> 2) & 63, k = idx >> 8;
        sm[OFF_W0P + idx] = Whh0[(g * 64 + jj) * 64 + k];
    }
    for (int idx = tid; idx < 6 * 64 * 4; idx += NTHREADS) {
        int g = idx & 3, jj = (idx >> 2) & 63, k = idx >> 8;
        sm[OFF_WX0P + idx] = Wih0[(g * 64 + jj) * 6 + k];
    }
    // zero both dup h arrays (contiguous: 4*BTILE*H floats)
    for (int idx = tid; idx < BTILE * H * 4; idx += NTHREADS)
        sm[OFF_HA + idx] = 0.0f;

    // per-thread biases from global (registers)
    const float bA0 = bih0[0 * 64 + j] + bhh0[0 * 64 + j];
    const float bA1 = bih0[1 * 64 + j] + bhh0[1 * 64 + j];
    const float bA2 = bih0[2 * 64 + j] + bhh0[2 * 64 + j];
    const float bA3 = bih0[3 * 64 + j] + bhh0[3 * 64 + j];
    const u64 bBif = packf2(bih1[0 * 64 + j] + bhh1[0 * 64 + j],
                            bih1[1 * 64 + j] + bhh1[1 * 64 + j]);
    const u64 bBgo = packf2(bih1[2 * 64 + j] + bhh1[2 * 64 + j],
                            bih1[3 * 64 + j] + bhh1[3 * 64 + j]);

    // x staging (threads 0..167 each own one (batch,feature) slot)
    const int xb = tid / IN;
    const int xf = tid - xb * IN;
    const bool xthr  = (tid < BTILE * IN);
    const bool xload = xthr && (b0 + xb < BB);
    float* XS = sm + OFF_XS;
    if (xthr) XS[tid] = xload ? x[((size_t)(b0 + xb) * TT + 0) * IN + xf] : 0.0f;

    __syncthreads();

    const ulonglong2* Wq1  = (const ulonglong2*)(sm + OFF_W1P);
    const ulonglong2* Wq0  = (const ulonglong2*)(sm + OFF_W0P);
    const float4*     Wx4  = (const float4*)(sm + OFF_WX0P);
    u64* hAu = (u64*)(sm + OFF_HA);
    u64* hBu = (u64*)(sm + OFF_HB);
    const ulonglong2* hA2 = (const ulonglong2*)(sm + OFF_HA);
    const ulonglong2* hB2 = (const ulonglong2*)(sm + OFF_HB);

    float cA[BPT], cB[BPT];
#pragma unroll
    for (int b = 0; b < BPT; ++b) { cA[b] = 0.f; cB[b] = 0.f; }

    for (int t = 0; t < TT; ++t) {
        // prefetch next x into register
        float xpre = 0.0f;
        if (t + 1 < TT && xload)
            xpre = x[((size_t)(b0 + xb) * TT + (t + 1)) * IN + xf];

        // ---------- layer 0: input part (scalar) + bias ----------
        float g0[BPT], g1[BPT], g2[BPT], g3[BPT];
#pragma unroll
        for (int b = 0; b < BPT; ++b) { g0[b] = bA0; g1[b] = bA1; g2[b] = bA2; g3[b] = bA3; }
#pragma unroll
        for (int k = 0; k < IN; ++k) {
            float4 w = Wx4[k * 64 + j];
#pragma unroll
            for (int b = 0; b < BPT; ++b) {
                float xv = XS[(bl0 + b) * IN + k];
                g0[b] = fmaf(xv, w.x, g0[b]);
                g1[b] = fmaf(xv, w.y, g1[b]);
                g2[b] = fmaf(xv, w.z, g2[b]);
                g3[b] = fmaf(xv, w.w, g3[b]);
            }
        }
        u64 aif[BPT], ago[BPT];
#pragma unroll
        for (int b = 0; b < BPT; ++b) {
            aif[b] = packf2(g0[b], g1[b]);
            ago[b] = packf2(g2[b], g3[b]);
        }
        // recurrent: Whh0 @ hA(t-1)
        gemm2(aif, ago, Wq0, hA2, j, bl0);

        float n[BPT];
#pragma unroll
        for (int b = 0; b < BPT; ++b) n[b] = cellact2(aif[b], ago[b], cA[b]);

        __syncthreads();                           // all reads of hA & XS done
#pragma unroll
        for (int b = 0; b < BPT; ++b) hAu[(bl0 + b) * H + j] = dup2(n[b]);
        if (xthr) XS[tid] = xpre;
        __syncthreads();                           // new hA / XS visible

        // ---------- layer 1 ----------
#pragma unroll
        for (int b = 0; b < BPT; ++b) { aif[b] = bBif; ago[b] = bBgo; }
        gemm2(aif, ago, Wq1,           hA2, j, bl0);   // Wih1 @ hA(t)
        gemm2(aif, ago, Wq1 + 64 * 64, hB2, j, bl0);   // Whh1 @ hB(t-1)

#pragma unroll
        for (int b = 0; b < BPT; ++b) n[b] = cellact2(aif[b], ago[b], cB[b]);

        __syncthreads();                           // all reads of hB done
#pragma unroll
        for (int b = 0; b < BPT; ++b) hBu[(bl0 + b) * H + j] = dup2(n[b]);
        // no sync here: next reads of hB happen after the 2 syncs above
    }

    // ---------- final FC: out = hB(T-1) @ Wfc^T + bfc ----------
    __syncthreads();                               // hB writes visible
    float* wfs = sm + OFF_HA;                      // reuse hA region
    if (tid < NOUT * H) wfs[tid] = Wfc[tid];
    if (tid < NOUT)     wfs[NOUT * H + tid] = bfc[tid];
    __syncthreads();

    if (j < NOUT) {
        const float* hBf = (const float*)hBu;      // dup pairs: stride 2 floats
#pragma unroll
        for (int b = 0; b < BPT; ++b) {
            int bglob = b0 + bl0 + b;
            if (bglob < BB) {
                float acc = wfs[NOUT * H + j];
                const float* wr = wfs + j * H;
                const float* hr = hBf + (bl0 + b) * H * 2;
#pragma unroll
                for (int k = 0; k < H; ++k) acc = fmaf(hr[2 * k], wr[k], acc);
                out[bglob * NOUT + j] = acc;
            }
        }
    }
}

extern "C" void kernel_launch(void* const* d_in, const int* in_sizes, int n_in,
                              void* d_out, int out_size)
{
    const float* x    = (const float*)d_in[0];
    const float* Wih0 = (const float*)d_in[1];
    const float* Whh0 = (const float*)d_in[2];
    const float* bih0 = (const float*)d_in[3];
    const float* bhh0 = (const float*)d_in[4];
    const float* Wih1 = (const float*)d_in[5];
    const float* Whh1 = (const float*)d_in[6];
    const float* bih1 = (const float*)d_in[7];
    const float* bhh1 = (const float*)d_in[8];
    const float* Wfc  = (const float*)d_in[9];
    const float* bfc  = (const float*)d_in[10];
    float* out = (float*)d_out;

    const size_t smem = (size_t)SMEM_FLOATS * sizeof(float);  // 232096 B
    cudaFuncSetAttribute(lstm2_kernel,
                         cudaFuncAttributeMaxDynamicSharedMemorySize, (int)smem);
    lstm2_kernel<<<NGRID, NTHREADS, smem>>>(x, Wih0, Whh0, bih0, bhh0,
                                            Wih1, Whh1, bih1, bhh1,
                                            Wfc, bfc, out);
}

// round 6
// speedup vs baseline: 1.0021x; 1.0005x over previous
#include <cuda_runtime.h>

typedef unsigned long long u64;

#define IN      6
#define H       64
#define BB      4096
#define TT      512
#define NOUT    3
#define BPT     7            // batches per thread
#define BTILE   28           // 4 batch-groups * 7
#define NTHREADS 256         // 64 units * 4 batch-groups
#define NGRID   147

// ---- shared memory layout (float units) ----
#define OFF_W1P   0                          // [k=128][j=64][g=4] floats (k<64: Wih1, k>=64: Whh1)
#define OFF_W0P   (OFF_W1P  + 128*64*4)      // [k=64][j=64][g=4]  Whh0
#define OFF_WX0P  (OFF_W0P  + 64*64*4)       // [k=6][j=64][g=4]   Wih0
#define OFF_HA    (OFF_WX0P + 6*64*4)        // [28][64] u64 duplicated pairs (2 floats each)
#define OFF_HB    (OFF_HA   + BTILE*H*2)
#define OFF_XS    (OFF_HB   + BTILE*H*2)     // [28][6] floats
#define SMEM_FLOATS (OFF_XS + BTILE*IN)      // 58024 floats = 232096 B

__device__ __forceinline__ float fexp2_(float x) {
    float y; asm("ex2.approx.f32 %0, %1;" : "=f"(y) : "f"(x)); return y;
}
__device__ __forceinline__ float frcp_(float x) {
    float y; asm("rcp.approx.f32 %0, %1;" : "=f"(y) : "f"(x)); return y;
}
__device__ __forceinline__ float sigm_(float x) {
    float e = fexp2_(-1.4426950408889634f * x);
    return frcp_(1.0f + e);
}
__device__ __forceinline__ float tanh_(float x) {
    float e = fexp2_(-2.8853900817779268f * x);
    return fmaf(2.0f, frcp_(1.0f + e), -1.0f);
}

// packed f32x2 fma: a += u * w (lane-wise)
__device__ __forceinline__ void ffma2(u64& a, u64 u, u64 w) {
    asm("fma.rn.f32x2 %0, %1, %2, %0;" : "+l"(a) : "l"(u), "l"(w));
}
__device__ __forceinline__ u64 packf2(float lo, float hi) {
    u64 r; asm("mov.b64 %0, {%1, %2};" : "=l"(r) : "f"(lo), "f"(hi)); return r;
}
__device__ __forceinline__ u64 dup2(float v) {
    u64 r; asm("mov.b64 %0, {%1, %1};" : "=l"(r) : "f"(v)); return r;
}
__device__ __forceinline__ void unpack2(u64 v, float& lo, float& hi) {
    asm("mov.b64 {%0, %1}, %2;" : "=f"(lo), "=f"(hi) : "l"(v));
}

// 64-deep K GEMM block, packed gates: aif[b] += h[k]*(Wi,Wf), ago[b] += h[k]*(Wg,Wo)
__device__ __forceinline__ void gemm2(
    u64 aif[BPT], u64 ago[BPT],
    const ulonglong2* __restrict__ Wq,   // [k][64] : (w_if, w_go) per (k,j)
    const ulonglong2* __restrict__ u2,   // [b][32] : ((h,h),(h,h)) pairs over k
    int j, int bl0)
{
#pragma unroll 2
    for (int k2 = 0; k2 < 32; ++k2) {
        ulonglong2 w0 = Wq[(2 * k2 + 0) * 64 + j];
        ulonglong2 w1 = Wq[(2 * k2 + 1) * 64 + j];
#pragma unroll
        for (int b = 0; b < BPT; ++b) {
            ulonglong2 u = u2[(bl0 + b) * 32 + k2];   // (dup h[2k2], dup h[2k2+1])
            ffma2(aif[b], u.x, w0.x);
            ffma2(ago[b], u.x, w0.y);
            ffma2(aif[b], u.y, w1.x);
            ffma2(ago[b], u.y, w1.y);
        }
    }
}

__device__ __forceinline__ float cellact2(u64 aif, u64 ago, float& c) {
    float ai, af, ag, ao;
    unpack2(aif, ai, af);
    unpack2(ago, ag, ao);
    float ig = sigm_(ai);
    float fg = sigm_(af);
    float gg = tanh_(ag);
    float og = sigm_(ao);
    c = fmaf(fg, c, ig * gg);
    return og * tanh_(c);
}

__global__ void __launch_bounds__(NTHREADS, 1)
lstm2_kernel(const float* __restrict__ x,
             const float* __restrict__ Wih0, const float* __restrict__ Whh0,
             const float* __restrict__ bih0, const float* __restrict__ bhh0,
             const float* __restrict__ Wih1, const float* __restrict__ Whh1,
             const float* __restrict__ bih1, const float* __restrict__ bhh1,
             const float* __restrict__ Wfc,  const float* __restrict__ bfc,
             float* __restrict__ out)
{
    extern __shared__ float sm[];
    const int tid = threadIdx.x;
    const int j   = tid & 63;        // hidden unit
    const int bg  = tid >> 6;        // batch group 0..3
    const int bl0 = bg * BPT;        // first local batch
    const int b0  = blockIdx.x * BTILE;

    // ---- pack weights into SMEM (gate-quad layout [k][j][g]) ----
    for (int idx = tid; idx < 128 * 64 * 4; idx += NTHREADS) {
        int g = idx & 3, jj = (idx >> 2) & 63, k = idx >> 8;
        sm[OFF_W1P + idx] = (k < 64) ? Wih1[(g * 64 + jj) * 64 + k]
                                     : Whh1[(g * 64 + jj) * 64 + (k - 64)];
    }
    for (int idx = tid; idx < 64 * 64 * 4; idx += NTHREADS) {
        int g = idx & 3, jj = (idx >> 2) & 63, k = idx >> 8;
        sm[OFF_W0P + idx] = Whh0[(g * 64 + jj) * 64 + k];
    }
    for (int idx = tid; idx < 6 * 64 * 4; idx += NTHREADS) {
        int g = idx & 3, jj = (idx >> 2) & 63, k = idx >> 8;
        sm[OFF_WX0P + idx] = Wih0[(g * 64 + jj) * 6 + k];
    }
    // zero both dup h arrays (contiguous: 4*BTILE*H floats)
    for (int idx = tid; idx < BTILE * H * 4; idx += NTHREADS)
        sm[OFF_HA + idx] = 0.0f;

    // per-thread biases from global (registers)
    const float bA0 = bih0[0 * 64 + j] + bhh0[0 * 64 + j];
    const float bA1 = bih0[1 * 64 + j] + bhh0[1 * 64 + j];
    const float bA2 = bih0[2 * 64 + j] + bhh0[2 * 64 + j];
    const float bA3 = bih0[3 * 64 + j] + bhh0[3 * 64 + j];
    const u64 bBif = packf2(bih1[0 * 64 + j] + bhh1[0 * 64 + j],
                            bih1[1 * 64 + j] + bhh1[1 * 64 + j]);
    const u64 bBgo = packf2(bih1[2 * 64 + j] + bhh1[2 * 64 + j],
                            bih1[3 * 64 + j] + bhh1[3 * 64 + j]);

    // x staging (threads 0..167 each own one (batch,feature) slot)
    const int xb = tid / IN;
    const int xf = tid - xb * IN;
    const bool xthr  = (tid < BTILE * IN);
    const bool xload = xthr && (b0 + xb < BB);
    float* XS = sm + OFF_XS;
    if (xthr) XS[tid] = xload ? x[((size_t)(b0 + xb) * TT + 0) * IN + xf] : 0.0f;

    __syncthreads();

    const ulonglong2* Wq1  = (const ulonglong2*)(sm + OFF_W1P);
    const ulonglong2* Wq0  = (const ulonglong2*)(sm + OFF_W0P);
    const float4*     Wx4  = (const float4*)(sm + OFF_WX0P);
    u64* hAu = (u64*)(sm + OFF_HA);
    u64* hBu = (u64*)(sm + OFF_HB);
    const ulonglong2* hA2 = (const ulonglong2*)(sm + OFF_HA);
    const ulonglong2* hB2 = (const ulonglong2*)(sm + OFF_HB);

    float cA[BPT], cB[BPT];
#pragma unroll
    for (int b = 0; b < BPT; ++b) { cA[b] = 0.f; cB[b] = 0.f; }

    for (int t = 0; t < TT; ++t) {
        // prefetch next x into register
        float xpre = 0.0f;
        if (t + 1 < TT && xload)
            xpre = x[((size_t)(b0 + xb) * TT + (t + 1)) * IN + xf];

        // ---------- layer 0: input part (scalar) + bias ----------
        float g0[BPT], g1[BPT], g2[BPT], g3[BPT];
#pragma unroll
        for (int b = 0; b < BPT; ++b) { g0[b] = bA0; g1[b] = bA1; g2[b] = bA2; g3[b] = bA3; }
#pragma unroll
        for (int k = 0; k < IN; ++k) {
            float4 w = Wx4[k * 64 + j];
#pragma unroll
            for (int b = 0; b < BPT; ++b) {
                float xv = XS[(bl0 + b) * IN + k];
                g0[b] = fmaf(xv, w.x, g0[b]);
                g1[b] = fmaf(xv, w.y, g1[b]);
                g2[b] = fmaf(xv, w.z, g2[b]);
                g3[b] = fmaf(xv, w.w, g3[b]);
            }
        }
        u64 aif[BPT], ago[BPT];
#pragma unroll
        for (int b = 0; b < BPT; ++b) {
            aif[b] = packf2(g0[b], g1[b]);
            ago[b] = packf2(g2[b], g3[b]);
        }
        // recurrent: Whh0 @ hA(t-1)
        gemm2(aif, ago, Wq0, hA2, j, bl0);

        float n[BPT];
#pragma unroll
        for (int b = 0; b < BPT; ++b) n[b] = cellact2(aif[b], ago[b], cA[b]);

        __syncthreads();                           // all reads of hA & XS done
#pragma unroll
        for (int b = 0; b < BPT; ++b) hAu[(bl0 + b) * H + j] = dup2(n[b]);
        if (xthr) XS[tid] = xpre;
        __syncthreads();                           // new hA / XS visible

        // ---------- layer 1 ----------
#pragma unroll
        for (int b = 0; b < BPT; ++b) { aif[b] = bBif; ago[b] = bBgo; }
        gemm2(aif, ago, Wq1,           hA2, j, bl0);   // Wih1 @ hA(t)
        gemm2(aif, ago, Wq1 + 64 * 64, hB2, j, bl0);   // Whh1 @ hB(t-1)

#pragma unroll
        for (int b = 0; b < BPT; ++b) n[b] = cellact2(aif[b], ago[b], cB[b]);

        __syncthreads();                           // all reads of hB done
#pragma unroll
        for (int b = 0; b < BPT; ++b) hBu[(bl0 + b) * H + j] = dup2(n[b]);
        // no sync here: next reads of hB happen after the 2 syncs above
    }

    // ---------- final FC: out = hB(T-1) @ Wfc^T + bfc ----------
    __syncthreads();                               // hB writes visible
    float* wfs = sm + OFF_HA;                      // reuse hA region
    if (tid < NOUT * H) wfs[tid] = Wfc[tid];
    if (tid < NOUT)     wfs[NOUT * H + tid] = bfc[tid];
    __syncthreads();

    if (j < NOUT) {
        const float* hBf = (const float*)hBu;      // dup pairs: stride 2 floats
#pragma unroll
        for (int b = 0; b < BPT; ++b) {
            int bglob = b0 + bl0 + b;
            if (bglob < BB) {
                float acc = wfs[NOUT * H + j];
                const float* wr = wfs + j * H;
                const float* hr = hBf + (bl0 + b) * H * 2;
#pragma unroll
                for (int k = 0; k < H; ++k) acc = fmaf(hr[2 * k], wr[k], acc);
                out[bglob * NOUT + j] = acc;
            }
        }
    }
}

extern "C" void kernel_launch(void* const* d_in, const int* in_sizes, int n_in,
                              void* d_out, int out_size)
{
    const float* x    = (const float*)d_in[0];
    const float* Wih0 = (const float*)d_in[1];
    const float* Whh0 = (const float*)d_in[2];
    const float* bih0 = (const float*)d_in[3];
    const float* bhh0 = (const float*)d_in[4];
    const float* Wih1 = (const float*)d_in[5];
    const float* Whh1 = (const float*)d_in[6];
    const float* bih1 = (const float*)d_in[7];
    const float* bhh1 = (const float*)d_in[8];
    const float* Wfc  = (const float*)d_in[9];
    const float* bfc  = (const float*)d_in[10];
    float* out = (float*)d_out;

    const size_t smem = (size_t)SMEM_FLOATS * sizeof(float);  // 232096 B
    cudaFuncSetAttribute(lstm2_kernel,
                         cudaFuncAttributeMaxDynamicSharedMemorySize, (int)smem);
    lstm2_kernel<<<NGRID, NTHREADS, smem>>>(x, Wih0, Whh0, bih0, bhh0,
                                            Wih1, Whh1, bih1, bhh1,
                                            Wfc, bfc, out);
}